// round 14
// baseline (speedup 1.0000x reference)
#include <cuda_runtime.h>
#include <math.h>

#define U 8388608UL
__device__ __align__(256) float g_pool[11*U + 393216];

// ---------------- helpers ----------------
__device__ __forceinline__ float tf32r(float v) {
    unsigned u;
    asm("cvt.rna.tf32.f32 %0, %1;" : "=r"(u) : "f"(v));
    return __uint_as_float(u);
}
__device__ __forceinline__ void mma_tf32(float* c, const unsigned* a, const unsigned* b) {
    asm volatile(
        "mma.sync.aligned.m16n8k8.row.col.f32.tf32.tf32.f32 "
        "{%0,%1,%2,%3},{%4,%5,%6,%7},{%8,%9},{%0,%1,%2,%3};"
        : "+f"(c[0]), "+f"(c[1]), "+f"(c[2]), "+f"(c[3])
        : "r"(a[0]), "r"(a[1]), "r"(a[2]), "r"(a[3]), "r"(b[0]), "r"(b[1]));
}

// ---------------- DWT ----------------
__global__ void dwt_kernel(const float* __restrict__ x, float* __restrict__ hllh,
                           float* __restrict__ yL, float* __restrict__ yHH)
{
    int i  = blockIdx.x;
    int cb = blockIdx.y;
    int b  = blockIdx.z;
    __shared__ float s[16][2][129];
    int tid = threadIdx.x;
    #pragma unroll
    for (int k = 0; k < 16; k++) {
        int e = tid + k*256;
        int cc = e >> 8, r = (e >> 7) & 1, col = e & 127;
        s[cc][r][col] = x[(((size_t)(b*128 + cb*16 + cc))*128 + 2*i + r)*128 + col];
    }
    __syncthreads();
    #pragma unroll
    for (int k = 0; k < 4; k++) {
        int e = tid + k*256;
        int cc = e & 15, j = e >> 4;
        float a  = s[cc][0][2*j], bb = s[cc][0][2*j+1];
        float c_ = s[cc][1][2*j], d  = s[cc][1][2*j+1];
        size_t token = (size_t)b*4096 + (size_t)i*64 + j;
        int c = cb*16 + cc;
        yL [token*128 + c]        = (a+bb+c_+d)*0.5f;
        yHH[token*128 + c]        = (a-bb-c_+d)*0.5f;
        hllh[token*256 + c]       = (a-bb+c_-d)*0.5f;
        hllh[token*256 + 128 + c] = (a+bb-c_-d)*0.5f;
    }
}

// ---------------- per-token LN stats ----------------
__global__ void ln_stats(const float* __restrict__ X, float* __restrict__ tm, float* __restrict__ tr)
{
    int wrp = threadIdx.x >> 5, lane = threadIdx.x & 31;
    size_t token = (size_t)blockIdx.x*8 + wrp;
    const float4 v = *(const float4*)&X[token*128 + lane*4];
    float s  = v.x+v.y+v.z+v.w;
    float ss = v.x*v.x+v.y*v.y+v.z*v.z+v.w*v.w;
    #pragma unroll
    for (int o = 16; o; o >>= 1) {
        s  += __shfl_xor_sync(0xffffffffu, s,  o);
        ss += __shfl_xor_sync(0xffffffffu, ss, o);
    }
    if (lane == 0) {
        float mean = s * (1.f/128.f);
        tm[token] = mean;
        tr[token] = rsqrtf(ss*(1.f/128.f) - mean*mean + 1e-5f);
    }
}

// ---------------- tf32 NT GEMM (prefetch; optional A-side subtract A2) ----------------
// C = epi(scale*(A-A2).B^T + bias) ; epi: 0 none, 1 gelu
__global__ __launch_bounds__(256, 2) void gemm_tf32(
    const float* __restrict__ A, size_t sAz, int lda,
    const float* __restrict__ B, size_t sBz, int ldb,
    float* __restrict__ C, size_t sCz, int ldc,
    int K, float scale, const float* __restrict__ bias,
    int epi, const float* __restrict__ A2)
{
    const float* Ab = A + (size_t)blockIdx.z * sAz;
    const float* Bb = B + (size_t)blockIdx.z * sBz;
    float* Cb = C + (size_t)blockIdx.z * sCz;
    int m0 = blockIdx.x * 128, n0 = blockIdx.y * 128;
    __shared__ float As[16][136], Bs[16][136];
    int tid = threadIdx.x;
    int wid = tid >> 5, lane = tid & 31;
    int g = lane >> 2, tig = lane & 3;
    int wm = (wid >> 1) * 32, wn = (wid & 1) * 64;
    float acc[2][8][4];
    #pragma unroll
    for (int i = 0; i < 2; i++)
        #pragma unroll
        for (int j = 0; j < 8; j++)
            #pragma unroll
            for (int q = 0; q < 4; q++) acc[i][j][q] = 0.f;

    int rowA = tid >> 2, kq = (tid & 3) * 4;
    float4 pa[2], pb[2], pa2[2];
    #pragma unroll
    for (int e = 0; e < 2; e++) {
        int r = rowA + e*64;
        pa[e] = *(const float4*)&Ab[(size_t)(m0 + r)*lda + kq];
        pb[e] = *(const float4*)&Bb[(size_t)(n0 + r)*ldb + kq];
        if (A2) pa2[e] = *(const float4*)&A2[(size_t)(m0 + r)*lda + kq];
    }
    for (int k0 = 0; k0 < K; k0 += 16) {
        #pragma unroll
        for (int e = 0; e < 2; e++) {
            int r = rowA + e*64;
            float ax = pa[e].x, ay = pa[e].y, az = pa[e].z, aw = pa[e].w;
            if (A2) { ax -= pa2[e].x; ay -= pa2[e].y; az -= pa2[e].z; aw -= pa2[e].w; }
            As[kq+0][r]=tf32r(ax); As[kq+1][r]=tf32r(ay);
            As[kq+2][r]=tf32r(az); As[kq+3][r]=tf32r(aw);
            Bs[kq+0][r]=tf32r(pb[e].x); Bs[kq+1][r]=tf32r(pb[e].y);
            Bs[kq+2][r]=tf32r(pb[e].z); Bs[kq+3][r]=tf32r(pb[e].w);
        }
        __syncthreads();
        if (k0 + 16 < K) {
            #pragma unroll
            for (int e = 0; e < 2; e++) {
                int r = rowA + e*64;
                pa[e] = *(const float4*)&Ab[(size_t)(m0 + r)*lda + k0 + 16 + kq];
                pb[e] = *(const float4*)&Bb[(size_t)(n0 + r)*ldb + k0 + 16 + kq];
                if (A2) pa2[e] = *(const float4*)&A2[(size_t)(m0 + r)*lda + k0 + 16 + kq];
            }
        }
        #pragma unroll
        for (int ks = 0; ks < 16; ks += 8) {
            unsigned af[2][4], bf[8][2];
            #pragma unroll
            for (int mi = 0; mi < 2; mi++) {
                af[mi][0] = __float_as_uint(As[ks+tig  ][wm+mi*16+g  ]);
                af[mi][1] = __float_as_uint(As[ks+tig  ][wm+mi*16+g+8]);
                af[mi][2] = __float_as_uint(As[ks+tig+4][wm+mi*16+g  ]);
                af[mi][3] = __float_as_uint(As[ks+tig+4][wm+mi*16+g+8]);
            }
            #pragma unroll
            for (int ni = 0; ni < 8; ni++) {
                bf[ni][0] = __float_as_uint(Bs[ks+tig  ][wn+ni*8+g]);
                bf[ni][1] = __float_as_uint(Bs[ks+tig+4][wn+ni*8+g]);
            }
            #pragma unroll
            for (int mi = 0; mi < 2; mi++)
                #pragma unroll
                for (int ni = 0; ni < 8; ni++)
                    mma_tf32(acc[mi][ni], af[mi], bf[ni]);
        }
        __syncthreads();
    }
    #pragma unroll
    for (int mi = 0; mi < 2; mi++)
        #pragma unroll
        for (int half = 0; half < 2; half++) {
            int m = m0 + wm + mi*16 + g + half*8;
            #pragma unroll
            for (int ni = 0; ni < 8; ni++) {
                int n = n0 + wn + ni*8 + 2*tig;
                float v0 = acc[mi][ni][half*2+0]*scale;
                float v1 = acc[mi][ni][half*2+1]*scale;
                if (bias) { v0 += bias[n]; v1 += bias[n+1]; }
                if (epi == 1) { v0 = v0*normcdff(v0); v1 = v1*normcdff(v1); }
                *(float2*)&Cb[(size_t)m*ldc + n] = make_float2(v0, v1);
            }
        }
}

// ---------------- FFN stage1 prep: wcat = gamma*w, u=sum(gamma*w), v=sum(beta*w) ----------------
__global__ void ffn1_prep(
    const float* __restrict__ fc1w, const float* __restrict__ divw,
    const float* __restrict__ actw, const float* __restrict__ f3aw,
    const float* __restrict__ ln1g, const float* __restrict__ ln1b,
    const float* __restrict__ ln3g, const float* __restrict__ ln3b,
    const float* __restrict__ fc1b, const float* __restrict__ divb,
    const float* __restrict__ actb, const float* __restrict__ f3ab,
    float* __restrict__ wcat, float* __restrict__ bcat,
    float* __restrict__ ucat, float* __restrict__ vcat)
{
    int n = blockIdx.x*128 + threadIdx.x;     // 0..511
    int gidx = n >> 7, nl = n & 127;
    const float* w = gidx==0?fc1w : gidx==1?divw : gidx==2?actw : f3aw;
    const float* gv = gidx==0?ln1g : gidx==3?ln3g : nullptr;
    const float* bv = gidx==0?ln1b : gidx==3?ln3b : nullptr;
    const float* bb = gidx==0?fc1b : gidx==1?divb : gidx==2?actb : f3ab;
    float u = 0.f, v = 0.f;
    for (int k = 0; k < 128; k++) {
        float wk = w[nl*128 + k];
        float gk = gv ? gv[k] : 1.f;
        float bk = bv ? bv[k] : 0.f;
        wcat[n*128 + k] = gk*wk;
        u += gk*wk; v += bk*wk;
    }
    bcat[n] = bb[nl]; ucat[n] = u; vcat[n] = v;
}

// ---------------- FFN stage1 fused GEMM: N=512 concat, LN via rank-1 epilogue ----------------
__global__ __launch_bounds__(256, 2) void gemm_ffn1(
    const float* __restrict__ att, const float* __restrict__ wcat,
    const float* __restrict__ bcat, const float* __restrict__ ucat,
    const float* __restrict__ vcat,
    const float* __restrict__ tm, const float* __restrict__ tr,
    float* __restrict__ x1g, float* __restrict__ dvg,
    float* __restrict__ gate, float* __restrict__ x3a)
{
    int grp = blockIdx.x;                 // 0..3
    int m0 = blockIdx.y * 128;
    const float* Bb = wcat + grp*16384;
    __shared__ float As[16][136], Bs[16][136];
    int tid = threadIdx.x;
    int wid = tid >> 5, lane = tid & 31;
    int g = lane >> 2, tig = lane & 3;
    int wm = (wid >> 1) * 32, wn = (wid & 1) * 64;
    float acc[2][8][4];
    #pragma unroll
    for (int i = 0; i < 2; i++)
        #pragma unroll
        for (int j = 0; j < 8; j++)
            #pragma unroll
            for (int q = 0; q < 4; q++) acc[i][j][q] = 0.f;

    int rowA = tid >> 2, kq = (tid & 3) * 4;
    float4 pa[2], pb[2];
    #pragma unroll
    for (int e = 0; e < 2; e++) {
        int r = rowA + e*64;
        pa[e] = *(const float4*)&att[(size_t)(m0 + r)*128 + kq];
        pb[e] = *(const float4*)&Bb[(size_t)r*128 + kq];
    }
    for (int k0 = 0; k0 < 128; k0 += 16) {
        #pragma unroll
        for (int e = 0; e < 2; e++) {
            int r = rowA + e*64;
            As[kq+0][r]=tf32r(pa[e].x); As[kq+1][r]=tf32r(pa[e].y);
            As[kq+2][r]=tf32r(pa[e].z); As[kq+3][r]=tf32r(pa[e].w);
            Bs[kq+0][r]=tf32r(pb[e].x); Bs[kq+1][r]=tf32r(pb[e].y);
            Bs[kq+2][r]=tf32r(pb[e].z); Bs[kq+3][r]=tf32r(pb[e].w);
        }
        __syncthreads();
        if (k0 + 16 < 128) {
            #pragma unroll
            for (int e = 0; e < 2; e++) {
                int r = rowA + e*64;
                pa[e] = *(const float4*)&att[(size_t)(m0 + r)*128 + k0 + 16 + kq];
                pb[e] = *(const float4*)&Bb[(size_t)r*128 + k0 + 16 + kq];
            }
        }
        #pragma unroll
        for (int ks = 0; ks < 16; ks += 8) {
            unsigned af[2][4], bf[8][2];
            #pragma unroll
            for (int mi = 0; mi < 2; mi++) {
                af[mi][0] = __float_as_uint(As[ks+tig  ][wm+mi*16+g  ]);
                af[mi][1] = __float_as_uint(As[ks+tig  ][wm+mi*16+g+8]);
                af[mi][2] = __float_as_uint(As[ks+tig+4][wm+mi*16+g  ]);
                af[mi][3] = __float_as_uint(As[ks+tig+4][wm+mi*16+g+8]);
            }
            #pragma unroll
            for (int ni = 0; ni < 8; ni++) {
                bf[ni][0] = __float_as_uint(Bs[ks+tig  ][wn+ni*8+g]);
                bf[ni][1] = __float_as_uint(Bs[ks+tig+4][wn+ni*8+g]);
            }
            #pragma unroll
            for (int mi = 0; mi < 2; mi++)
                #pragma unroll
                for (int ni = 0; ni < 8; ni++)
                    mma_tf32(acc[mi][ni], af[mi], bf[ni]);
        }
        __syncthreads();
    }
    bool isln = (grp == 0) || (grp == 3);
    float* out = grp==0 ? x1g : grp==1 ? dvg : grp==2 ? gate : x3a;
    #pragma unroll
    for (int mi = 0; mi < 2; mi++)
        #pragma unroll
        for (int half = 0; half < 2; half++) {
            int m = m0 + wm + mi*16 + g + half*8;
            float mu = tm[m], rs = tr[m];
            #pragma unroll
            for (int ni = 0; ni < 8; ni++) {
                int n = wn + ni*8 + 2*tig;
                int gn = grp*128 + n;
                float v0 = acc[mi][ni][half*2+0];
                float v1 = acc[mi][ni][half*2+1];
                if (isln) {
                    v0 = rs*v0 - rs*mu*ucat[gn]   + vcat[gn];
                    v1 = rs*v1 - rs*mu*ucat[gn+1] + vcat[gn+1];
                }
                v0 += bcat[gn]; v1 += bcat[gn+1];
                if (grp == 2) { v0 = 1.f/(1.f+expf(-v0)); v1 = 1.f/(1.f+expf(-v1)); }
                else          { v0 = v0*normcdff(v0);     v1 = v1*normcdff(v1); }
                *(float2*)&out[(size_t)m*128 + n] = make_float2(v0, v1);
            }
        }
}

// ---------------- conv l1: implicit GEMM, K-slice 64, dynamic smem ----------------
__global__ __launch_bounds__(256, 2) void conv_l1_tf32(
    const float* __restrict__ x, const float* __restrict__ w,
    const float* __restrict__ bias, float* __restrict__ dw)
{
    extern __shared__ float cs[];
    float* patch = cs;            // 8*6*132 = 6336
    float* As = cs + 6336;        // 64*136 = 8704
    float* Bs = As + 8704;        // 64*136
    int blk = blockIdx.x;
    int b   = blockIdx.z;
    int oh0 = blk*2;
    int tid = threadIdx.x;
    int wid = tid >> 5, lane = tid & 31;
    int g = lane >> 2, tig = lane & 3;
    int wm = (wid >> 1) * 32, wn = (wid & 1) * 64;
    float acc[2][8][4];
    #pragma unroll
    for (int i = 0; i < 2; i++)
        #pragma unroll
        for (int j = 0; j < 8; j++)
            #pragma unroll
            for (int q = 0; q < 4; q++) acc[i][j][q] = 0.f;

    int t = tid & 127, khalf = tid >> 7;
    int ohl = t >> 6, ow = t & 63;
    int coB = tid >> 1, kbB = (tid & 1) * 32;

    for (int ci0 = 0; ci0 < 128; ci0 += 8) {
        for (int e = tid; e < 8*6*130; e += 256) {
            int cil = e / 780;
            int rem = e - cil*780;
            int r = rem / 130, cc = rem - r*130;
            int gr = 2*oh0 - 1 + r, gc = cc - 1;
            float v = 0.f;
            if ((unsigned)gr < 128u && (unsigned)gc < 128u)
                v = x[(((size_t)b*128 + ci0 + cil)*128 + gr)*128 + gc];
            patch[cil*792 + r*132 + cc] = tf32r(v);
        }
        __syncthreads();
        #pragma unroll
        for (int s = 0; s < 2; s++) {
            #pragma unroll
            for (int i = 0; i < 32; i++) {
                int kk = khalf*32 + i;
                int cil = s*4 + (kk >> 4);
                int kh = (kk >> 2) & 3, kw = kk & 3;
                As[kk*136 + t] = patch[cil*792 + (2*ohl + kh)*132 + 2*ow + kw];
            }
            {
                const float* wp = &w[(size_t)coB*2048 + (ci0 + s*4)*16 + kbB];
                #pragma unroll
                for (int j = 0; j < 8; j++) {
                    float4 v = *(const float4*)&wp[j*4];
                    Bs[(kbB+j*4+0)*136 + coB] = tf32r(v.x);
                    Bs[(kbB+j*4+1)*136 + coB] = tf32r(v.y);
                    Bs[(kbB+j*4+2)*136 + coB] = tf32r(v.z);
                    Bs[(kbB+j*4+3)*136 + coB] = tf32r(v.w);
                }
            }
            __syncthreads();
            #pragma unroll
            for (int ks = 0; ks < 64; ks += 8) {
                unsigned af[2][4], bf[8][2];
                #pragma unroll
                for (int mi = 0; mi < 2; mi++) {
                    af[mi][0] = __float_as_uint(As[(ks+tig  )*136 + wm+mi*16+g  ]);
                    af[mi][1] = __float_as_uint(As[(ks+tig  )*136 + wm+mi*16+g+8]);
                    af[mi][2] = __float_as_uint(As[(ks+tig+4)*136 + wm+mi*16+g  ]);
                    af[mi][3] = __float_as_uint(As[(ks+tig+4)*136 + wm+mi*16+g+8]);
                }
                #pragma unroll
                for (int ni = 0; ni < 8; ni++) {
                    bf[ni][0] = __float_as_uint(Bs[(ks+tig  )*136 + wn+ni*8+g]);
                    bf[ni][1] = __float_as_uint(Bs[(ks+tig+4)*136 + wn+ni*8+g]);
                }
                #pragma unroll
                for (int mi = 0; mi < 2; mi++)
                    #pragma unroll
                    for (int ni = 0; ni < 8; ni++)
                        mma_tf32(acc[mi][ni], af[mi], bf[ni]);
            }
            __syncthreads();
        }
    }
    #pragma unroll
    for (int mi = 0; mi < 2; mi++)
        #pragma unroll
        for (int half = 0; half < 2; half++) {
            int midx = wm + mi*16 + g + half*8;
            size_t token = (size_t)b*4096 + (size_t)blk*128 + midx;
            #pragma unroll
            for (int ni = 0; ni < 8; ni++) {
                int n = wn + ni*8 + 2*tig;
                float v0 = fmaxf(acc[mi][ni][half*2+0] + bias[n],   0.f);
                float v1 = fmaxf(acc[mi][ni][half*2+1] + bias[n+1], 0.f);
                *(float2*)&dw[token*128 + n] = make_float2(v0, v1);
            }
        }
}

// ---------------- row softmax stats on S^T (warp per row, coalesced) ----------------
__global__ void col_stats(const float* __restrict__ St, float* __restrict__ cmax, float* __restrict__ csum)
{
    int row = blockIdx.x*8 + (threadIdx.x >> 5);
    int lane = threadIdx.x & 31;
    const float* r = St + (size_t)row*512;
    float4 v[4];
    #pragma unroll
    for (int i = 0; i < 4; i++) v[i] = *(const float4*)&r[lane*4 + i*128];
    float m = v[0].x;
    #pragma unroll
    for (int i = 0; i < 4; i++) {
        m = fmaxf(m, fmaxf(fmaxf(v[i].x, v[i].y), fmaxf(v[i].z, v[i].w)));
    }
    #pragma unroll
    for (int o = 16; o; o >>= 1) m = fmaxf(m, __shfl_xor_sync(0xffffffffu, m, o));
    float s = 0.f;
    #pragma unroll
    for (int i = 0; i < 4; i++)
        s += expf(v[i].x-m) + expf(v[i].y-m) + expf(v[i].z-m) + expf(v[i].w-m);
    #pragma unroll
    for (int o = 16; o; o >>= 1) s += __shfl_xor_sync(0xffffffffu, s, o);
    if (lane == 0) { cmax[row] = m; csum[row] = s; }
}

// ---------------- PV GEMM on S^T: O[q,c] = sum_k exp(St[k,q]-m_k)/s_k * V[k,c] ----------------
__global__ __launch_bounds__(256, 2) void gemm_pv_tf32(
    const float* __restrict__ St, const float* __restrict__ V,
    const float* __restrict__ cmax, const float* __restrict__ csum,
    float* __restrict__ O)
{
    int z = blockIdx.z;
    int m0 = blockIdx.x*128;
    const float* Sz = St + (size_t)z*262144;
    const float* Vz = V + (size_t)z*65536;
    const float* cm = cmax + z*512;
    const float* cs = csum + z*512;
    float* Oz = O + (size_t)z*65536;
    __shared__ float As[16][136], Bs[16][136];
    int tid = threadIdx.x;
    int wid = tid >> 5, lane = tid & 31;
    int g = lane >> 2, tig = lane & 3;
    int wm = (wid >> 1) * 32, wn = (wid & 1) * 64;
    float acc[2][8][4];
    #pragma unroll
    for (int i = 0; i < 2; i++)
        #pragma unroll
        for (int j = 0; j < 8; j++)
            #pragma unroll
            for (int q = 0; q < 4; q++) acc[i][j][q] = 0.f;

    int kkA = tid >> 4, q8 = (tid & 15) * 8;
    int n4 = (tid & 31) * 4, kkB = tid >> 5;
    float4 pa0, pa1, pb[2];
    float pcm, pcs[2];
    pa0 = *(const float4*)&Sz[(size_t)kkA*512 + m0 + q8];
    pa1 = *(const float4*)&Sz[(size_t)kkA*512 + m0 + q8 + 4];
    pcm = cm[kkA];
    #pragma unroll
    for (int e = 0; e < 2; e++) {
        pb[e] = *(const float4*)&Vz[(size_t)(kkB + e*8)*128 + n4];
        pcs[e] = cs[kkB + e*8];
    }
    for (int k0 = 0; k0 < 512; k0 += 16) {
        *(float4*)&As[kkA][q8] = make_float4(
            tf32r(expf(pa0.x - pcm)), tf32r(expf(pa0.y - pcm)),
            tf32r(expf(pa0.z - pcm)), tf32r(expf(pa0.w - pcm)));
        *(float4*)&As[kkA][q8+4] = make_float4(
            tf32r(expf(pa1.x - pcm)), tf32r(expf(pa1.y - pcm)),
            tf32r(expf(pa1.z - pcm)), tf32r(expf(pa1.w - pcm)));
        #pragma unroll
        for (int e = 0; e < 2; e++) {
            int kk = kkB + e*8;
            float rs = 1.0f / pcs[e];
            Bs[kk][n4+0] = tf32r(pb[e].x*rs);
            Bs[kk][n4+1] = tf32r(pb[e].y*rs);
            Bs[kk][n4+2] = tf32r(pb[e].z*rs);
            Bs[kk][n4+3] = tf32r(pb[e].w*rs);
        }
        __syncthreads();
        if (k0 + 16 < 512) {
            pa0 = *(const float4*)&Sz[(size_t)(k0 + 16 + kkA)*512 + m0 + q8];
            pa1 = *(const float4*)&Sz[(size_t)(k0 + 16 + kkA)*512 + m0 + q8 + 4];
            pcm = cm[k0 + 16 + kkA];
            #pragma unroll
            for (int e = 0; e < 2; e++) {
                pb[e] = *(const float4*)&Vz[(size_t)(k0 + 16 + kkB + e*8)*128 + n4];
                pcs[e] = cs[k0 + 16 + kkB + e*8];
            }
        }
        #pragma unroll
        for (int ks = 0; ks < 16; ks += 8) {
            unsigned af[2][4], bf[8][2];
            #pragma unroll
            for (int mi = 0; mi < 2; mi++) {
                af[mi][0] = __float_as_uint(As[ks+tig  ][wm+mi*16+g  ]);
                af[mi][1] = __float_as_uint(As[ks+tig  ][wm+mi*16+g+8]);
                af[mi][2] = __float_as_uint(As[ks+tig+4][wm+mi*16+g  ]);
                af[mi][3] = __float_as_uint(As[ks+tig+4][wm+mi*16+g+8]);
            }
            #pragma unroll
            for (int ni = 0; ni < 8; ni++) {
                bf[ni][0] = __float_as_uint(Bs[ks+tig  ][wn+ni*8+g]);
                bf[ni][1] = __float_as_uint(Bs[ks+tig+4][wn+ni*8+g]);
            }
            #pragma unroll
            for (int mi = 0; mi < 2; mi++)
                #pragma unroll
                for (int ni = 0; ni < 8; ni++)
                    mma_tf32(acc[mi][ni], af[mi], bf[ni]);
        }
        __syncthreads();
    }
    #pragma unroll
    for (int mi = 0; mi < 2; mi++)
        #pragma unroll
        for (int half = 0; half < 2; half++) {
            int m = m0 + wm + mi*16 + g + half*8;
            #pragma unroll
            for (int ni = 0; ni < 8; ni++) {
                int n = wn + ni*8 + 2*tig;
                *(float2*)&Oz[(size_t)m*128 + n] =
                    make_float2(acc[mi][ni][half*2+0], acc[mi][ni][half*2+1]);
            }
        }
}

// ---------------- out = gate * ln(x2+x3) ----------------
__global__ void ln_final(const float* __restrict__ X2, const float* __restrict__ X3,
                         const float* __restrict__ G, const float* __restrict__ gv,
                         const float* __restrict__ bv, float* __restrict__ out)
{
    int wrp = threadIdx.x >> 5, lane = threadIdx.x & 31;
    size_t token = (size_t)blockIdx.x*8 + wrp;
    float4 a = *(const float4*)&X2[token*128 + lane*4];
    float4 c = *(const float4*)&X3[token*128 + lane*4];
    float4 v = make_float4(a.x+c.x, a.y+c.y, a.z+c.z, a.w+c.w);
    float s  = v.x+v.y+v.z+v.w;
    float ss = v.x*v.x+v.y*v.y+v.z*v.z+v.w*v.w;
    #pragma unroll
    for (int o = 16; o; o >>= 1) {
        s  += __shfl_xor_sync(0xffffffffu, s,  o);
        ss += __shfl_xor_sync(0xffffffffu, ss, o);
    }
    float mean = s * (1.f/128.f);
    float rstd = rsqrtf(ss*(1.f/128.f) - mean*mean + 1e-5f);
    float4 g = *(const float4*)&gv[lane*4];
    float4 b = *(const float4*)&bv[lane*4];
    float4 gt = *(const float4*)&G[token*128 + lane*4];
    float4 o;
    o.x = gt.x * ((v.x-mean)*rstd*g.x + b.x);
    o.y = gt.y * ((v.y-mean)*rstd*g.y + b.y);
    o.z = gt.z * ((v.z-mean)*rstd*g.z + b.z);
    o.w = gt.w * ((v.w-mean)*rstd*g.w + b.w);
    *(float4*)&out[token*128 + lane*4] = o;
}

// ---------------- final combine ----------------
__global__ void final_kernel(const float* __restrict__ x, const float* __restrict__ ffn,
                             const float* __restrict__ yt, const float* __restrict__ dwb,
                             float* __restrict__ out)
{
    int oh = blockIdx.x;
    int cq = blockIdx.y;
    int b  = blockIdx.z;
    int c0 = cq*32;
    __shared__ float s_f[64*33], s_y[64*33], s_d[64*33];
    int tid = threadIdx.x;
    size_t tok0 = (size_t)b*4096 + (size_t)oh*64;
    #pragma unroll
    for (int k = 0; k < 8; k++) {
        int e = tid + k*256;
        int cl = e & 31, t = e >> 5;
        size_t ga = (tok0 + t)*128 + c0 + cl;
        s_f[t*33+cl] = ffn[ga];
        s_y[t*33+cl] = yt[ga];
        s_d[t*33+cl] = dwb[ga];
    }
    float ph = (float)oh * (127.0f/63.0f);
    int y0 = min((int)floorf(ph), 127);
    int y1 = min(y0+1, 127);
    float wy = ph - (float)y0;
    __syncthreads();
    #pragma unroll
    for (int k = 0; k < 8; k++) {
        int e = tid + k*256;
        int ow = e & 63, cl = e >> 6;
        float pw = (float)ow * (127.0f/63.0f);
        int x0 = min((int)floorf(pw), 127);
        int x1 = min(x0+1, 127);
        float wx = pw - (float)x0;
        const float* xr = x + (((size_t)b*128 + c0 + cl)*128)*128;
        float r0 = xr[(size_t)y0*128 + x0]*(1.f-wx) + xr[(size_t)y0*128 + x1]*wx;
        float r1 = xr[(size_t)y1*128 + x0]*(1.f-wx) + xr[(size_t)y1*128 + x1]*wx;
        float down = r0*(1.f-wy) + r1*wy;
        float v = s_f[ow*33+cl]*(down - s_d[ow*33+cl]) + s_y[ow*33+cl];
        out[(((size_t)b*128 + c0+cl)*64 + oh)*64 + ow] = v;
    }
}

extern "C" void kernel_launch(void* const* d_in, const int* in_sizes, int n_in,
                              void* d_out, int out_size)
{
    (void)in_sizes; (void)n_in; (void)out_size;
    const float* x      = (const float*)d_in[0];
    const float* conv1w = (const float*)d_in[1];
    const float* conv1b = (const float*)d_in[2];
    const float* l1w    = (const float*)d_in[3];
    const float* l1b    = (const float*)d_in[4];
    const float* ln1g   = (const float*)d_in[5];
    const float* ln1b   = (const float*)d_in[6];
    const float* fc1w   = (const float*)d_in[7];
    const float* fc1b   = (const float*)d_in[8];
    const float* divw   = (const float*)d_in[9];
    const float* divb   = (const float*)d_in[10];
    const float* fc2w   = (const float*)d_in[11];
    const float* fc2b   = (const float*)d_in[12];
    const float* ln3g   = (const float*)d_in[13];
    const float* ln3b   = (const float*)d_in[14];
    const float* fc3aw  = (const float*)d_in[15];
    const float* fc3ab  = (const float*)d_in[16];
    const float* fc3bw  = (const float*)d_in[17];
    const float* fc3bb  = (const float*)d_in[18];
    const float* lnng   = (const float*)d_in[19];
    const float* lnnb   = (const float*)d_in[20];
    const float* actw   = (const float*)d_in[21];
    const float* actb   = (const float*)d_in[22];
    float* out = (float*)d_out;

    float* pool = nullptr;
    cudaGetSymbolAddress((void**)&pool, g_pool);

    float* yL    = pool + 0*U;
    float* yHH   = pool + 1*U;
    float* hllh  = pool + 2*U;   // 2U..4U
    float* y     = pool + 4*U;
    float* St    = pool + 5*U;   // 5U..9U
    float* att   = pool + 2*U;   // reuse hllh lo
    float* dvg   = pool + 3*U;   // reuse hllh hi
    float* x3a   = pool + 5*U;   // reuse St
    float* x2    = pool + 6*U;
    float* x3    = pool + 7*U;
    float* gate  = pool + 0*U;   // reuse yL
    float* ffn   = pool + 1*U;   // reuse yHH
    float* x1g   = pool + 9*U;
    float* dw    = pool + 10*U;
    float* cmax  = pool + 11*U;
    float* csum  = pool + 11*U + 65536;
    float* tmean = pool + 11*U + 131072;
    float* trstd = pool + 11*U + 196608;
    float* wcat  = pool + 11*U + 262144;
    float* bcat  = pool + 11*U + 327680;
    float* ucat  = pool + 11*U + 328192;
    float* vcat  = pool + 11*U + 328704;

    static bool attr_set = false;
    if (!attr_set) {
        cudaFuncSetAttribute(conv_l1_tf32, cudaFuncAttributeMaxDynamicSharedMemorySize, 94976);
        attr_set = true;
    }

    // 1. DWT
    dwt_kernel<<<dim3(64,8,16), 256>>>(x, hllh, yL, yHH);
    // 2. conv1 (1x1 as GEMM)
    gemm_tf32<<<dim3(512,1,1), 256>>>(hllh, 0, 256, conv1w, 0, 256,
                                      y, 0, 128, 256, 1.0f, conv1b, 0, nullptr);
    // 3. S^T = K Q^T * 8^-0.5  (A=y keys, B=yL queries)
    gemm_tf32<<<dim3(4,4,128), 256>>>(y, 65536, 128, yL, 65536, 128,
                                      St, 262144, 512, 128, 0.35355339059327f, nullptr, 0, nullptr);
    // 4. row softmax stats on S^T (coalesced)
    col_stats<<<8192, 256>>>(St, cmax, csum);
    // 5. att = P @ V
    gemm_pv_tf32<<<dim3(4,1,128), 256>>>(St, yHH, cmax, csum, att);
    // 6. token LN stats of att
    ln_stats<<<8192, 256>>>(att, tmean, trstd);
    // 7. FFN stage1 prep + fused N=512 GEMM
    ffn1_prep<<<4, 128>>>(fc1w, divw, actw, fc3aw, ln1g, ln1b, ln3g, ln3b,
                          fc1b, divb, actb, fc3ab, wcat, bcat, ucat, vcat);
    gemm_ffn1<<<dim3(4,512,1), 256>>>(att, wcat, bcat, ucat, vcat, tmean, trstd,
                                      x1g, dvg, gate, x3a);
    // 8. x2 = gelu((dvg - x1g) @ fc2^T + b)
    gemm_tf32<<<dim3(512,1,1), 256>>>(dvg, 0, 128, fc2w, 0, 128, x2, 0, 128,
                                      128, 1.f, fc2b, 1, x1g);
    // 9. x3 = x3a @ fc3b^T + b
    gemm_tf32<<<dim3(512,1,1), 256>>>(x3a, 0, 128, fc3bw, 0, 128, x3, 0, 128,
                                      128, 1.f, fc3bb, 0, nullptr);
    // 10. ffn = gate * ln(x2+x3)
    ln_final<<<8192, 256>>>(x2, x3, gate, lnng, lnnb, ffn);
    // 11. conv l1 (K-slice 64)
    conv_l1_tf32<<<dim3(32,1,16), 256, 94976>>>(x, l1w, l1b, dw);
    // 12. combine
    final_kernel<<<dim3(64,4,16), 256>>>(x, ffn, y, dw, out);
}